// round 2
// baseline (speedup 1.0000x reference)
#include <cuda_runtime.h>

// Problem constants
#define Bv 16
#define Vv 1024
#define Dv 512
#define Hv 8
#define HDv 64

// Scratch (static device globals: no allocation allowed in kernel_launch)
__device__ float g_q[Bv*Hv*Vv*HDv];
__device__ float g_k[Bv*Hv*Vv*HDv];
__device__ float g_v[Bv*Hv*Vv*HDv];
__device__ float g_o[Bv*Vv*Dv];

// ---------------------------------------------------------------------------
// Projection GEMM: out = X (16384x512) @ W^T (512x512), scattered to
// (B,H,V,HD) layout. blockIdx.z selects which of Wq/Wk/Wv and q/k/v dst.
// 128x128 tile, BK=8, 256 threads, 8x8 per thread (split 4+4 halves).
// ---------------------------------------------------------------------------
__global__ __launch_bounds__(256) void proj_kernel(
    const float* __restrict__ X,
    const float* __restrict__ Wq,
    const float* __restrict__ Wk,
    const float* __restrict__ Wv)
{
    const float* W;
    float* dst;
    if (blockIdx.z == 0)      { W = Wq; dst = g_q; }
    else if (blockIdx.z == 1) { W = Wk; dst = g_k; }
    else                      { W = Wv; dst = g_v; }

    __shared__ float As[8][128];
    __shared__ float Bs[8][128];

    const int tid = threadIdx.x;
    const int m0 = blockIdx.y * 128;
    const int n0 = blockIdx.x * 128;
    const int lr = tid >> 1;            // 0..127
    const int lc = (tid & 1) * 4;       // 0 or 4
    const int tx = tid & 15;
    const int ty = tid >> 4;

    const float* Xp = X + (size_t)(m0 + lr) * Dv + lc;
    const float* Wp = W + (size_t)(n0 + lr) * Dv + lc;

    float acc[8][8];
#pragma unroll
    for (int i = 0; i < 8; i++)
#pragma unroll
        for (int j = 0; j < 8; j++) acc[i][j] = 0.f;

    for (int k0 = 0; k0 < Dv; k0 += 8) {
        float4 a4 = *(const float4*)(Xp + k0);
        float4 b4 = *(const float4*)(Wp + k0);
        __syncthreads();
        As[lc + 0][lr] = a4.x; As[lc + 1][lr] = a4.y;
        As[lc + 2][lr] = a4.z; As[lc + 3][lr] = a4.w;
        Bs[lc + 0][lr] = b4.x; Bs[lc + 1][lr] = b4.y;
        Bs[lc + 2][lr] = b4.z; Bs[lc + 3][lr] = b4.w;
        __syncthreads();
#pragma unroll
        for (int kk = 0; kk < 8; kk++) {
            float4 a0 = *(const float4*)&As[kk][ty * 4];
            float4 a1 = *(const float4*)&As[kk][64 + ty * 4];
            float4 b0 = *(const float4*)&Bs[kk][tx * 4];
            float4 b1 = *(const float4*)&Bs[kk][64 + tx * 4];
            float ar[8] = {a0.x, a0.y, a0.z, a0.w, a1.x, a1.y, a1.z, a1.w};
            float br[8] = {b0.x, b0.y, b0.z, b0.w, b1.x, b1.y, b1.z, b1.w};
#pragma unroll
            for (int i = 0; i < 8; i++)
#pragma unroll
                for (int j = 0; j < 8; j++) acc[i][j] += ar[i] * br[j];
        }
    }

    // Epilogue: scatter to (B, H, V, HD)
#pragma unroll
    for (int i = 0; i < 8; i++) {
        int r = m0 + ((i < 4) ? (ty * 4 + i) : (64 + ty * 4 + (i - 4)));
        int bb = r >> 10;           // / V
        int vi = r & 1023;          // % V
#pragma unroll
        for (int j = 0; j < 8; j++) {
            int c = n0 + ((j < 4) ? (tx * 4 + j) : (64 + tx * 4 + (j - 4)));
            int h  = c >> 6;        // / HD
            int hd = c & 63;        // % HD
            dst[(((bb * Hv + h) * Vv) + vi) * HDv + hd] = acc[i][j];
        }
    }
}

// ---------------------------------------------------------------------------
// Flash attention: one block per (b*H+h, q-chunk of 256 rows).
// Thread t owns query row q0+t: q[64] and O[64] live in registers.
// K/V tiles of 32x64 in smem (uniform-address broadcast reads).
// hop_matrix tile staged as uchar in smem (values 0..8), row stride 36
// bytes -> conflict-free byte reads (9 coprime with 32).
// ---------------------------------------------------------------------------
__global__ __launch_bounds__(256) void attn_kernel(
    const float* __restrict__ rpe,   // (H, 9)
    const int*   __restrict__ hop)   // (V, V)
{
    const int bh = blockIdx.x;       // 0..127
    const int b  = bh >> 3;
    const int h  = bh & 7;
    const int q0 = blockIdx.y * 256;
    const int t  = threadIdx.x;

    __shared__ float Ksh[32][64];
    __shared__ float Vsh[32][64];
    __shared__ unsigned char hop_sh[256][36];
    __shared__ float rpe_sh[16];

    if (t < 9) rpe_sh[t] = rpe[h * 9 + t];

    // Load this thread's query row into registers
    float q[64];
    {
        const float* qp = g_q + (size_t)(bh * Vv + q0 + t) * HDv;
#pragma unroll
        for (int d = 0; d < 64; d += 4) {
            float4 v = *(const float4*)(qp + d);
            q[d] = v.x; q[d + 1] = v.y; q[d + 2] = v.z; q[d + 3] = v.w;
        }
    }
    __syncthreads();   // rpe_sh visible to all before first tile

    float O[64];
#pragma unroll
    for (int d = 0; d < 64; d++) O[d] = 0.f;
    float mmax = -1e30f;
    float l = 0.f;

    const float scale = 0.125f;  // 1/sqrt(64)

    for (int kt = 0; kt < Vv; kt += 32) {
        // --- load K/V tile: 32 rows x 64 cols, coalesced ---
        {
            int r = t >> 3;            // 0..31
            int c = (t & 7) * 8;       // 0,8,...,56
            const float* kp = g_k + (size_t)(bh * Vv + kt + r) * HDv + c;
            const float* vp = g_v + (size_t)(bh * Vv + kt + r) * HDv + c;
            *(float4*)&Ksh[r][c]     = *(const float4*)kp;
            *(float4*)&Ksh[r][c + 4] = *(const float4*)(kp + 4);
            *(float4*)&Vsh[r][c]     = *(const float4*)vp;
            *(float4*)&Vsh[r][c + 4] = *(const float4*)(vp + 4);
        }
        // --- load hop tile: my row, 32 ints -> bytes ---
        {
            const int* hp = hop + (size_t)(q0 + t) * Vv + kt;
#pragma unroll
            for (int i = 0; i < 8; i++) {
                int4 hv = *(const int4*)(hp + 4 * i);
                *(uchar4*)&hop_sh[t][4 * i] =
                    make_uchar4((unsigned char)hv.x, (unsigned char)hv.y,
                                (unsigned char)hv.z, (unsigned char)hv.w);
            }
        }
        __syncthreads();

        // --- scores for this tile ---
        float sv[32];
#pragma unroll
        for (int j = 0; j < 32; j++) {
            float s0 = 0.f, s1 = 0.f, s2 = 0.f, s3 = 0.f;
            const float4* kp4 = (const float4*)Ksh[j];
#pragma unroll
            for (int d4 = 0; d4 < 16; d4++) {
                float4 kv = kp4[d4];
                s0 += q[4 * d4 + 0] * kv.x;
                s1 += q[4 * d4 + 1] * kv.y;
                s2 += q[4 * d4 + 2] * kv.z;
                s3 += q[4 * d4 + 3] * kv.w;
            }
            float s = (s0 + s1) + (s2 + s3);
            sv[j] = s * scale + rpe_sh[hop_sh[t][j]];
        }

        // --- online softmax update ---
        float tm = sv[0];
#pragma unroll
        for (int j = 1; j < 32; j++) tm = fmaxf(tm, sv[j]);
        float mn = fmaxf(mmax, tm);
        float alpha = __expf(mmax - mn);
        l *= alpha;
#pragma unroll
        for (int d = 0; d < 64; d++) O[d] *= alpha;

#pragma unroll
        for (int j = 0; j < 32; j++) {
            float p = __expf(sv[j] - mn);
            l += p;
            const float4* vp4 = (const float4*)Vsh[j];
#pragma unroll
            for (int d4 = 0; d4 < 16; d4++) {
                float4 vv = vp4[d4];
                O[4 * d4 + 0] += p * vv.x;
                O[4 * d4 + 1] += p * vv.y;
                O[4 * d4 + 2] += p * vv.z;
                O[4 * d4 + 3] += p * vv.w;
            }
        }
        mmax = mn;
        __syncthreads();   // protect this tile's smem before next overwrite
    }

    // Normalize and write to (B, V, D) layout
    float inv = 1.f / l;
    float* op = g_o + (size_t)(b * Vv + q0 + t) * Dv + h * HDv;
#pragma unroll
    for (int d = 0; d < 64; d += 4) {
        float4 v;
        v.x = O[d] * inv; v.y = O[d + 1] * inv;
        v.z = O[d + 2] * inv; v.w = O[d + 3] * inv;
        *(float4*)(op + d) = v;
    }
}

// ---------------------------------------------------------------------------
// Output GEMM: out = g_o (16384x512) @ Wo^T (512x512) + bo
// ---------------------------------------------------------------------------
__global__ __launch_bounds__(256) void out_kernel(
    const float* __restrict__ Wo,
    const float* __restrict__ bo,
    float* __restrict__ out)
{
    __shared__ float As[8][128];
    __shared__ float Bs[8][128];

    const int tid = threadIdx.x;
    const int m0 = blockIdx.y * 128;
    const int n0 = blockIdx.x * 128;
    const int lr = tid >> 1;
    const int lc = (tid & 1) * 4;
    const int tx = tid & 15;
    const int ty = tid >> 4;

    const float* Xp = g_o + (size_t)(m0 + lr) * Dv + lc;
    const float* Wp = Wo  + (size_t)(n0 + lr) * Dv + lc;

    float acc[8][8];
#pragma unroll
    for (int i = 0; i < 8; i++)
#pragma unroll
        for (int j = 0; j < 8; j++) acc[i][j] = 0.f;

    for (int k0 = 0; k0 < Dv; k0 += 8) {
        float4 a4 = *(const float4*)(Xp + k0);
        float4 b4 = *(const float4*)(Wp + k0);
        __syncthreads();
        As[lc + 0][lr] = a4.x; As[lc + 1][lr] = a4.y;
        As[lc + 2][lr] = a4.z; As[lc + 3][lr] = a4.w;
        Bs[lc + 0][lr] = b4.x; Bs[lc + 1][lr] = b4.y;
        Bs[lc + 2][lr] = b4.z; Bs[lc + 3][lr] = b4.w;
        __syncthreads();
#pragma unroll
        for (int kk = 0; kk < 8; kk++) {
            float4 a0 = *(const float4*)&As[kk][ty * 4];
            float4 a1 = *(const float4*)&As[kk][64 + ty * 4];
            float4 b0 = *(const float4*)&Bs[kk][tx * 4];
            float4 b1 = *(const float4*)&Bs[kk][64 + tx * 4];
            float ar[8] = {a0.x, a0.y, a0.z, a0.w, a1.x, a1.y, a1.z, a1.w};
            float br[8] = {b0.x, b0.y, b0.z, b0.w, b1.x, b1.y, b1.z, b1.w};
#pragma unroll
            for (int i = 0; i < 8; i++)
#pragma unroll
                for (int j = 0; j < 8; j++) acc[i][j] += ar[i] * br[j];
        }
    }

#pragma unroll
    for (int i = 0; i < 8; i++) {
        int r = m0 + ((i < 4) ? (ty * 4 + i) : (64 + ty * 4 + (i - 4)));
#pragma unroll
        for (int j = 0; j < 8; j++) {
            int c = n0 + ((j < 4) ? (tx * 4 + j) : (64 + tx * 4 + (j - 4)));
            out[(size_t)r * Dv + c] = acc[i][j] + bo[c];
        }
    }
}

// ---------------------------------------------------------------------------
// Entry point. Inputs (metadata order):
//   0: x (B,V,D) f32   1: Wq (D,D)   2: Wk   3: Wv   4: Wo
//   5: bo (D,)         6: rpe (H, MAXHOP+1)  7: hop_matrix (V,V) int32
// Output: (B,V,D) f32
// ---------------------------------------------------------------------------
extern "C" void kernel_launch(void* const* d_in, const int* in_sizes, int n_in,
                              void* d_out, int out_size)
{
    const float* x   = (const float*)d_in[0];
    const float* Wq  = (const float*)d_in[1];
    const float* Wk  = (const float*)d_in[2];
    const float* Wv  = (const float*)d_in[3];
    const float* Wo  = (const float*)d_in[4];
    const float* bo  = (const float*)d_in[5];
    const float* rpe = (const float*)d_in[6];
    const int*   hop = (const int*)d_in[7];
    float* out = (float*)d_out;

    (void)in_sizes; (void)n_in; (void)out_size;

    // 1) QKV projections: M=16384, N=512 -> grid (4, 128, 3)
    proj_kernel<<<dim3(4, 128, 3), 256>>>(x, Wq, Wk, Wv);

    // 2) Flash attention: (B*H, V/256) blocks of 256 threads
    attn_kernel<<<dim3(Bv * Hv, Vv / 256), 256>>>(rpe, hop);

    // 3) Output projection + bias
    out_kernel<<<dim3(4, 128), 256>>>(Wo, bo, out);
}

// round 4
// speedup vs baseline: 1.0010x; 1.0010x over previous
#include <cuda_runtime.h>

// Problem constants
#define Bv 16
#define Vv 1024
#define Dv 512
#define Hv 8
#define HDv 64

// Scratch (static device globals: no allocation allowed in kernel_launch)
__device__ float g_q[Bv*Hv*Vv*HDv];
__device__ float g_k[Bv*Hv*Vv*HDv];
__device__ float g_v[Bv*Hv*Vv*HDv];
__device__ float g_o[Bv*Vv*Dv];

// ---------------------------------------------------------------------------
// Projection GEMM: out = X (16384x512) @ W^T (512x512), scattered to
// (B,H,V,HD) layout. blockIdx.z selects which of Wq/Wk/Wv and q/k/v dst.
// 128x128 tile, BK=8, 256 threads, 8x8 per thread (split 4+4 halves).
// ---------------------------------------------------------------------------
__global__ __launch_bounds__(256) void proj_kernel(
    const float* __restrict__ X,
    const float* __restrict__ Wq,
    const float* __restrict__ Wk,
    const float* __restrict__ Wv)
{
    const float* W;
    float* dst;
    if (blockIdx.z == 0)      { W = Wq; dst = g_q; }
    else if (blockIdx.z == 1) { W = Wk; dst = g_k; }
    else                      { W = Wv; dst = g_v; }

    __shared__ float As[8][128];
    __shared__ float Bs[8][128];

    const int tid = threadIdx.x;
    const int m0 = blockIdx.y * 128;
    const int n0 = blockIdx.x * 128;
    const int lr = tid >> 1;            // 0..127
    const int lc = (tid & 1) * 4;       // 0 or 4
    const int tx = tid & 15;
    const int ty = tid >> 4;

    const float* Xp = X + (size_t)(m0 + lr) * Dv + lc;
    const float* Wp = W + (size_t)(n0 + lr) * Dv + lc;

    float acc[8][8];
#pragma unroll
    for (int i = 0; i < 8; i++)
#pragma unroll
        for (int j = 0; j < 8; j++) acc[i][j] = 0.f;

    for (int k0 = 0; k0 < Dv; k0 += 8) {
        float4 a4 = *(const float4*)(Xp + k0);
        float4 b4 = *(const float4*)(Wp + k0);
        __syncthreads();
        As[lc + 0][lr] = a4.x; As[lc + 1][lr] = a4.y;
        As[lc + 2][lr] = a4.z; As[lc + 3][lr] = a4.w;
        Bs[lc + 0][lr] = b4.x; Bs[lc + 1][lr] = b4.y;
        Bs[lc + 2][lr] = b4.z; Bs[lc + 3][lr] = b4.w;
        __syncthreads();
#pragma unroll
        for (int kk = 0; kk < 8; kk++) {
            float4 a0 = *(const float4*)&As[kk][ty * 4];
            float4 a1 = *(const float4*)&As[kk][64 + ty * 4];
            float4 b0 = *(const float4*)&Bs[kk][tx * 4];
            float4 b1 = *(const float4*)&Bs[kk][64 + tx * 4];
            float ar[8] = {a0.x, a0.y, a0.z, a0.w, a1.x, a1.y, a1.z, a1.w};
            float br[8] = {b0.x, b0.y, b0.z, b0.w, b1.x, b1.y, b1.z, b1.w};
#pragma unroll
            for (int i = 0; i < 8; i++)
#pragma unroll
                for (int j = 0; j < 8; j++) acc[i][j] += ar[i] * br[j];
        }
    }

    // Epilogue: scatter to (B, H, V, HD)
#pragma unroll
    for (int i = 0; i < 8; i++) {
        int r = m0 + ((i < 4) ? (ty * 4 + i) : (64 + ty * 4 + (i - 4)));
        int bb = r >> 10;           // / V
        int vi = r & 1023;          // % V
#pragma unroll
        for (int j = 0; j < 8; j++) {
            int c = n0 + ((j < 4) ? (tx * 4 + j) : (64 + tx * 4 + (j - 4)));
            int h  = c >> 6;        // / HD
            int hd = c & 63;        // % HD
            dst[(((bb * Hv + h) * Vv) + vi) * HDv + hd] = acc[i][j];
        }
    }
}

// ---------------------------------------------------------------------------
// Flash attention: one block per (b*H+h, q-chunk of 256 rows).
// Thread t owns query row q0+t: q[64] and O[64] live in registers.
// K/V tiles of 32x64 in smem (uniform-address broadcast reads).
// hop_matrix tile staged as uchar in smem (values 0..8), row stride 36
// bytes -> conflict-free byte reads (9 coprime with 32).
// ---------------------------------------------------------------------------
__global__ __launch_bounds__(256) void attn_kernel(
    const float* __restrict__ rpe,   // (H, 9)
    const int*   __restrict__ hop)   // (V, V)
{
    const int bh = blockIdx.x;       // 0..127
    const int b  = bh >> 3;
    const int h  = bh & 7;
    const int q0 = blockIdx.y * 256;
    const int t  = threadIdx.x;

    __shared__ float Ksh[32][64];
    __shared__ float Vsh[32][64];
    __shared__ unsigned char hop_sh[256][36];
    __shared__ float rpe_sh[16];

    if (t < 9) rpe_sh[t] = rpe[h * 9 + t];

    // Load this thread's query row into registers
    float q[64];
    {
        const float* qp = g_q + (size_t)(bh * Vv + q0 + t) * HDv;
#pragma unroll
        for (int d = 0; d < 64; d += 4) {
            float4 v = *(const float4*)(qp + d);
            q[d] = v.x; q[d + 1] = v.y; q[d + 2] = v.z; q[d + 3] = v.w;
        }
    }
    __syncthreads();   // rpe_sh visible to all before first tile

    float O[64];
#pragma unroll
    for (int d = 0; d < 64; d++) O[d] = 0.f;
    float mmax = -1e30f;
    float l = 0.f;

    const float scale = 0.125f;  // 1/sqrt(64)

    for (int kt = 0; kt < Vv; kt += 32) {
        // --- load K/V tile: 32 rows x 64 cols, coalesced ---
        {
            int r = t >> 3;            // 0..31
            int c = (t & 7) * 8;       // 0,8,...,56
            const float* kp = g_k + (size_t)(bh * Vv + kt + r) * HDv + c;
            const float* vp = g_v + (size_t)(bh * Vv + kt + r) * HDv + c;
            *(float4*)&Ksh[r][c]     = *(const float4*)kp;
            *(float4*)&Ksh[r][c + 4] = *(const float4*)(kp + 4);
            *(float4*)&Vsh[r][c]     = *(const float4*)vp;
            *(float4*)&Vsh[r][c + 4] = *(const float4*)(vp + 4);
        }
        // --- load hop tile: my row, 32 ints -> bytes ---
        {
            const int* hp = hop + (size_t)(q0 + t) * Vv + kt;
#pragma unroll
            for (int i = 0; i < 8; i++) {
                int4 hv = *(const int4*)(hp + 4 * i);
                *(uchar4*)&hop_sh[t][4 * i] =
                    make_uchar4((unsigned char)hv.x, (unsigned char)hv.y,
                                (unsigned char)hv.z, (unsigned char)hv.w);
            }
        }
        __syncthreads();

        // --- scores for this tile ---
        float sv[32];
#pragma unroll
        for (int j = 0; j < 32; j++) {
            float s0 = 0.f, s1 = 0.f, s2 = 0.f, s3 = 0.f;
            const float4* kp4 = (const float4*)Ksh[j];
#pragma unroll
            for (int d4 = 0; d4 < 16; d4++) {
                float4 kv = kp4[d4];
                s0 += q[4 * d4 + 0] * kv.x;
                s1 += q[4 * d4 + 1] * kv.y;
                s2 += q[4 * d4 + 2] * kv.z;
                s3 += q[4 * d4 + 3] * kv.w;
            }
            float s = (s0 + s1) + (s2 + s3);
            sv[j] = s * scale + rpe_sh[hop_sh[t][j]];
        }

        // --- online softmax update ---
        float tm = sv[0];
#pragma unroll
        for (int j = 1; j < 32; j++) tm = fmaxf(tm, sv[j]);
        float mn = fmaxf(mmax, tm);
        float alpha = __expf(mmax - mn);
        l *= alpha;
#pragma unroll
        for (int d = 0; d < 64; d++) O[d] *= alpha;

#pragma unroll
        for (int j = 0; j < 32; j++) {
            float p = __expf(sv[j] - mn);
            l += p;
            const float4* vp4 = (const float4*)Vsh[j];
#pragma unroll
            for (int d4 = 0; d4 < 16; d4++) {
                float4 vv = vp4[d4];
                O[4 * d4 + 0] += p * vv.x;
                O[4 * d4 + 1] += p * vv.y;
                O[4 * d4 + 2] += p * vv.z;
                O[4 * d4 + 3] += p * vv.w;
            }
        }
        mmax = mn;
        __syncthreads();   // protect this tile's smem before next overwrite
    }

    // Normalize and write to (B, V, D) layout
    float inv = 1.f / l;
    float* op = g_o + (size_t)(b * Vv + q0 + t) * Dv + h * HDv;
#pragma unroll
    for (int d = 0; d < 64; d += 4) {
        float4 v;
        v.x = O[d] * inv; v.y = O[d + 1] * inv;
        v.z = O[d + 2] * inv; v.w = O[d + 3] * inv;
        *(float4*)(op + d) = v;
    }
}

// ---------------------------------------------------------------------------
// Output GEMM: out = g_o (16384x512) @ Wo^T (512x512) + bo
// ---------------------------------------------------------------------------
__global__ __launch_bounds__(256) void out_kernel(
    const float* __restrict__ Wo,
    const float* __restrict__ bo,
    float* __restrict__ out)
{
    __shared__ float As[8][128];
    __shared__ float Bs[8][128];

    const int tid = threadIdx.x;
    const int m0 = blockIdx.y * 128;
    const int n0 = blockIdx.x * 128;
    const int lr = tid >> 1;
    const int lc = (tid & 1) * 4;
    const int tx = tid & 15;
    const int ty = tid >> 4;

    const float* Xp = g_o + (size_t)(m0 + lr) * Dv + lc;
    const float* Wp = Wo  + (size_t)(n0 + lr) * Dv + lc;

    float acc[8][8];
#pragma unroll
    for (int i = 0; i < 8; i++)
#pragma unroll
        for (int j = 0; j < 8; j++) acc[i][j] = 0.f;

    for (int k0 = 0; k0 < Dv; k0 += 8) {
        float4 a4 = *(const float4*)(Xp + k0);
        float4 b4 = *(const float4*)(Wp + k0);
        __syncthreads();
        As[lc + 0][lr] = a4.x; As[lc + 1][lr] = a4.y;
        As[lc + 2][lr] = a4.z; As[lc + 3][lr] = a4.w;
        Bs[lc + 0][lr] = b4.x; Bs[lc + 1][lr] = b4.y;
        Bs[lc + 2][lr] = b4.z; Bs[lc + 3][lr] = b4.w;
        __syncthreads();
#pragma unroll
        for (int kk = 0; kk < 8; kk++) {
            float4 a0 = *(const float4*)&As[kk][ty * 4];
            float4 a1 = *(const float4*)&As[kk][64 + ty * 4];
            float4 b0 = *(const float4*)&Bs[kk][tx * 4];
            float4 b1 = *(const float4*)&Bs[kk][64 + tx * 4];
            float ar[8] = {a0.x, a0.y, a0.z, a0.w, a1.x, a1.y, a1.z, a1.w};
            float br[8] = {b0.x, b0.y, b0.z, b0.w, b1.x, b1.y, b1.z, b1.w};
#pragma unroll
            for (int i = 0; i < 8; i++)
#pragma unroll
                for (int j = 0; j < 8; j++) acc[i][j] += ar[i] * br[j];
        }
    }

#pragma unroll
    for (int i = 0; i < 8; i++) {
        int r = m0 + ((i < 4) ? (ty * 4 + i) : (64 + ty * 4 + (i - 4)));
#pragma unroll
        for (int j = 0; j < 8; j++) {
            int c = n0 + ((j < 4) ? (tx * 4 + j) : (64 + tx * 4 + (j - 4)));
            out[(size_t)r * Dv + c] = acc[i][j] + bo[c];
        }
    }
}

// ---------------------------------------------------------------------------
// Entry point. Inputs (metadata order):
//   0: x (B,V,D) f32   1: Wq (D,D)   2: Wk   3: Wv   4: Wo
//   5: bo (D,)         6: rpe (H, MAXHOP+1)  7: hop_matrix (V,V) int32
// Output: (B,V,D) f32
// ---------------------------------------------------------------------------
extern "C" void kernel_launch(void* const* d_in, const int* in_sizes, int n_in,
                              void* d_out, int out_size)
{
    const float* x   = (const float*)d_in[0];
    const float* Wq  = (const float*)d_in[1];
    const float* Wk  = (const float*)d_in[2];
    const float* Wv  = (const float*)d_in[3];
    const float* Wo  = (const float*)d_in[4];
    const float* bo  = (const float*)d_in[5];
    const float* rpe = (const float*)d_in[6];
    const int*   hop = (const int*)d_in[7];
    float* out = (float*)d_out;

    (void)in_sizes; (void)n_in; (void)out_size;

    // 1) QKV projections: M=16384, N=512 -> grid (4, 128, 3)
    proj_kernel<<<dim3(4, 128, 3), 256>>>(x, Wq, Wk, Wv);

    // 2) Flash attention: (B*H, V/256) blocks of 256 threads
    attn_kernel<<<dim3(Bv * Hv, Vv / 256), 256>>>(rpe, hop);

    // 3) Output projection + bias
    out_kernel<<<dim3(4, 128), 256>>>(Wo, bo, out);
}

// round 8
// speedup vs baseline: 2.4941x; 2.4915x over previous
#include <cuda_runtime.h>
#include <cuda_bf16.h>

#define Bv 16
#define Vv 1024
#define Dv 512
#define Hv 8
#define HDv 64

// Split bf16 scratch: packed uint = 2 bf16 (even dim low, odd dim high)
__device__ unsigned g_xhi[4194304], g_xlo[4194304];     // X rows: 256 uints
__device__ unsigned g_whi[4][131072], g_wlo[4][131072]; // Wq,Wk,Wv,Wo
__device__ unsigned g_qhi[4194304], g_qlo[4194304];     // (B*H, V, 32 uints)
__device__ unsigned g_khi[4194304], g_klo[4194304];
__device__ unsigned g_vhi[4194304], g_vlo[4194304];
__device__ unsigned g_ohi[4194304], g_olo[4194304];     // (B*V, 256 uints)
__device__ unsigned char g_hop8[1048576];

__device__ __forceinline__ void split2(float x, float y, unsigned &h, unsigned &l) {
    __nv_bfloat16 hx = __float2bfloat16_rn(x), hy = __float2bfloat16_rn(y);
    __nv_bfloat16 lx = __float2bfloat16_rn(x - __bfloat162float(hx));
    __nv_bfloat16 ly = __float2bfloat16_rn(y - __bfloat162float(hy));
    h = ((unsigned)__bfloat16_as_ushort(hy) << 16) | __bfloat16_as_ushort(hx);
    l = ((unsigned)__bfloat16_as_ushort(ly) << 16) | __bfloat16_as_ushort(lx);
}
__device__ __forceinline__ void mma_bf16(float c[4], const unsigned a[4],
                                         unsigned b0, unsigned b1) {
    asm volatile(
        "mma.sync.aligned.m16n8k16.row.col.f32.bf16.bf16.f32 "
        "{%0,%1,%2,%3}, {%4,%5,%6,%7}, {%8,%9}, {%0,%1,%2,%3};"
        : "+f"(c[0]), "+f"(c[1]), "+f"(c[2]), "+f"(c[3])
        : "r"(a[0]), "r"(a[1]), "r"(a[2]), "r"(a[3]), "r"(b0), "r"(b1));
}
__device__ __forceinline__ void ldsm4t(unsigned r[4], const void* p) {
    unsigned a = (unsigned)__cvta_generic_to_shared(p);
    asm volatile("ldmatrix.sync.aligned.m8n8.x4.trans.shared.b16 {%0,%1,%2,%3}, [%4];"
        : "=r"(r[0]), "=r"(r[1]), "=r"(r[2]), "=r"(r[3]) : "r"(a));
}
__device__ __forceinline__ float ex2(float x) {
    float y; asm("ex2.approx.f32 %0, %1;" : "=f"(y) : "f"(x)); return y;
}

// which: 0=x, 1..4 = Wq,Wk,Wv,Wo
__global__ void split_kernel(const float* __restrict__ in, int which, int n2) {
    int i = blockIdx.x * blockDim.x + threadIdx.x;
    if (i >= n2) return;
    unsigned *hi, *lo;
    if (which == 0) { hi = g_xhi; lo = g_xlo; }
    else            { hi = g_whi[which - 1]; lo = g_wlo[which - 1]; }
    float2 v = ((const float2*)in)[i];
    unsigned h, l; split2(v.x, v.y, h, l);
    hi[i] = h; lo[i] = l;
}
__global__ void hop8_kernel(const int* __restrict__ hop, int n4) {
    int i = blockIdx.x * blockDim.x + threadIdx.x;
    if (i >= n4) return;
    int4 v = ((const int4*)hop)[i];
    ((unsigned*)g_hop8)[i] = (unsigned)(v.x & 0xff) | ((unsigned)(v.y & 0xff) << 8) |
        ((unsigned)(v.z & 0xff) << 16) | ((unsigned)(v.w & 0xff) << 24);
}

// ---------------------------------------------------------------------------
// Shared 128x128 bf16x3 GEMM: C = A(128x512) * B(512x128)^T, rows k-contig
// (256 uints/row). 8 warps: warp w -> (w&3)*32 m-rows x (w>>2)*64 n-cols.
// ---------------------------------------------------------------------------
struct GSmem { unsigned Ah[128][20], Al[128][20], Bh[128][20], Bl[128][20]; };

__device__ __forceinline__ void gemm128(
    GSmem& sm,
    const unsigned* __restrict__ Agh, const unsigned* __restrict__ Agl,
    const unsigned* __restrict__ Bgh, const unsigned* __restrict__ Bgl,
    int m0, int n0, int t, float C[2][8][4])
{
    const int w = t >> 5, lane = t & 31, g = lane >> 2, tg = lane & 3;
    const int wm = w & 3, wn = w >> 2;
#pragma unroll
    for (int mt = 0; mt < 2; mt++)
#pragma unroll
        for (int nt = 0; nt < 8; nt++)
#pragma unroll
            for (int j = 0; j < 4; j++) C[mt][nt][j] = 0.f;

    const int srow = t >> 1, scb = (t & 1) * 8;
    const unsigned* Ap  = Agh + (size_t)(m0 + srow) * 256 + scb;
    const unsigned* Alp = Agl + (size_t)(m0 + srow) * 256 + scb;
    const unsigned* Bp  = Bgh + (size_t)(n0 + srow) * 256 + scb;
    const unsigned* Blp = Bgl + (size_t)(n0 + srow) * 256 + scb;

    for (int k0 = 0; k0 < 256; k0 += 16) {
        uint4 a0 = *(const uint4*)(Ap + k0),  a1 = *(const uint4*)(Ap + k0 + 4);
        uint4 a2 = *(const uint4*)(Alp + k0), a3 = *(const uint4*)(Alp + k0 + 4);
        uint4 b0 = *(const uint4*)(Bp + k0),  b1 = *(const uint4*)(Bp + k0 + 4);
        uint4 b2 = *(const uint4*)(Blp + k0), b3 = *(const uint4*)(Blp + k0 + 4);
        __syncthreads();
        *(uint4*)&sm.Ah[srow][scb] = a0; *(uint4*)&sm.Ah[srow][scb + 4] = a1;
        *(uint4*)&sm.Al[srow][scb] = a2; *(uint4*)&sm.Al[srow][scb + 4] = a3;
        *(uint4*)&sm.Bh[srow][scb] = b0; *(uint4*)&sm.Bh[srow][scb + 4] = b1;
        *(uint4*)&sm.Bl[srow][scb] = b2; *(uint4*)&sm.Bl[srow][scb + 4] = b3;
        __syncthreads();
#pragma unroll
        for (int ks = 0; ks < 2; ks++) {
            unsigned ah[2][4], al[2][4];
#pragma unroll
            for (int mt = 0; mt < 2; mt++) {
                int r = wm * 32 + mt * 16 + g, c = 8 * ks + tg;
                ah[mt][0] = sm.Ah[r][c];     ah[mt][1] = sm.Ah[r + 8][c];
                ah[mt][2] = sm.Ah[r][c + 4]; ah[mt][3] = sm.Ah[r + 8][c + 4];
                al[mt][0] = sm.Al[r][c];     al[mt][1] = sm.Al[r + 8][c];
                al[mt][2] = sm.Al[r][c + 4]; al[mt][3] = sm.Al[r + 8][c + 4];
            }
#pragma unroll
            for (int nt = 0; nt < 8; nt++) {
                int n = wn * 64 + nt * 8 + g, c = 8 * ks + tg;
                unsigned bh0 = sm.Bh[n][c], bh1 = sm.Bh[n][c + 4];
                unsigned bl0 = sm.Bl[n][c], bl1 = sm.Bl[n][c + 4];
#pragma unroll
                for (int mt = 0; mt < 2; mt++) {
                    mma_bf16(C[mt][nt], ah[mt], bh0, bh1);
                    mma_bf16(C[mt][nt], ah[mt], bl0, bl1);
                    mma_bf16(C[mt][nt], al[mt], bh0, bh1);
                }
            }
        }
    }
}

__global__ __launch_bounds__(256) void proj_mma() {
    __shared__ GSmem sm;
    const unsigned *Bgh = g_whi[blockIdx.z], *Bgl = g_wlo[blockIdx.z];
    unsigned *Dh, *Dl;
    if (blockIdx.z == 0)      { Dh = g_qhi; Dl = g_qlo; }
    else if (blockIdx.z == 1) { Dh = g_khi; Dl = g_klo; }
    else                      { Dh = g_vhi; Dl = g_vlo; }

    const int t = threadIdx.x;
    const int m0 = blockIdx.y * 128, n0 = blockIdx.x * 128;
    float C[2][8][4];
    gemm128(sm, g_xhi, g_xlo, Bgh, Bgl, m0, n0, t, C);

    const int w = t >> 5, lane = t & 31, g = lane >> 2, tg = lane & 3;
    const int wm = w & 3, wn = w >> 2;
#pragma unroll
    for (int mt = 0; mt < 2; mt++) {
        int row = m0 + wm * 32 + mt * 16 + g;
        int bb = row >> 10, vi = row & 1023;
#pragma unroll
        for (int nt = 0; nt < 8; nt++) {
            int col = n0 + wn * 64 + nt * 8 + 2 * tg;
            int hh = col >> 6, hd2 = (col & 63) >> 1;
            size_t idx = ((size_t)(bb * 8 + hh) * 1024 + vi) * 32 + hd2;
            unsigned uh, ul;
            split2(C[mt][nt][0], C[mt][nt][1], uh, ul);
            Dh[idx] = uh; Dl[idx] = ul;
            split2(C[mt][nt][2], C[mt][nt][3], uh, ul);
            Dh[idx + 256] = uh; Dl[idx + 256] = ul;     // row+8 -> vi+8
        }
    }
}

// ---------------------------------------------------------------------------
// Flash attention (bf16x3 mma). Block: 1 bh x 128 q rows; warp w: 16 q rows.
// Softmax in log2 domain (rpe pre-scaled by log2e; score scale folded in).
// ---------------------------------------------------------------------------
__global__ __launch_bounds__(256) void attn_mma(const float* __restrict__ rpe) {
    const int bh = blockIdx.x, b = bh >> 3, h = bh & 7;
    const int q0 = blockIdx.y * 128;
    const int t = threadIdx.x, w = t >> 5, lane = t & 31;
    const int g = lane >> 2, tg = lane & 3;
    const float L2E = 1.4426950408889634f;

    __shared__ unsigned Khi[64][36], Klo[64][36], Vhi[64][36], Vlo[64][36];
    __shared__ unsigned char hopsh[128][80];
    __shared__ float rpesh[12];

    if (t < 9) rpesh[t] = rpe[h * 9 + t] * L2E;

    unsigned qh[4][4], ql[4][4];
    {
        const unsigned* qhp = g_qhi + (size_t)bh * 1024 * 32;
        const unsigned* qlp = g_qlo + (size_t)bh * 1024 * 32;
        int r0 = (q0 + 16 * w + g) * 32, r8 = r0 + 256;
#pragma unroll
        for (int ks = 0; ks < 4; ks++) {
            int c = 8 * ks + tg;
            qh[ks][0] = qhp[r0 + c]; qh[ks][1] = qhp[r8 + c];
            qh[ks][2] = qhp[r0 + c + 4]; qh[ks][3] = qhp[r8 + c + 4];
            ql[ks][0] = qlp[r0 + c]; ql[ks][1] = qlp[r8 + c];
            ql[ks][2] = qlp[r0 + c + 4]; ql[ks][3] = qlp[r8 + c + 4];
        }
    }

    float O[8][4];
#pragma unroll
    for (int nt = 0; nt < 8; nt++)
#pragma unroll
        for (int j = 0; j < 4; j++) O[nt][j] = 0.f;
    float mr0 = -1e30f, mr1 = -1e30f, l0 = 0.f, l1 = 0.f;
    const size_t kvbase = (size_t)bh * 1024 * 32;
    const float sc = 0.125f * L2E;

    for (int kt = 0; kt < 1024; kt += 64) {
        {   // stage K/V hi/lo (64 keys x 32 uints)
            int key = t >> 2, cb = (t & 3) * 8;
            size_t go = kvbase + (size_t)(kt + key) * 32 + cb;
            const uint4* p;
            p = (const uint4*)(g_khi + go);
            *(uint4*)&Khi[key][cb] = p[0]; *(uint4*)&Khi[key][cb + 4] = p[1];
            p = (const uint4*)(g_klo + go);
            *(uint4*)&Klo[key][cb] = p[0]; *(uint4*)&Klo[key][cb + 4] = p[1];
            p = (const uint4*)(g_vhi + go);
            *(uint4*)&Vhi[key][cb] = p[0]; *(uint4*)&Vhi[key][cb + 4] = p[1];
            p = (const uint4*)(g_vlo + go);
            *(uint4*)&Vlo[key][cb] = p[0]; *(uint4*)&Vlo[key][cb + 4] = p[1];
        }
        {   // stage hop bytes (128 q x 64 keys)
            int r = t >> 1, c0 = (t & 1) * 32;
            const uint4* p = (const uint4*)(g_hop8 + (size_t)(q0 + r) * 1024 + kt + c0);
            *(uint4*)&hopsh[r][c0] = p[0];
            *(uint4*)&hopsh[r][c0 + 16] = p[1];
        }
        __syncthreads();

        float S[8][4];
#pragma unroll
        for (int nt = 0; nt < 8; nt++)
#pragma unroll
            for (int j = 0; j < 4; j++) S[nt][j] = 0.f;
#pragma unroll
        for (int ks = 0; ks < 4; ks++)
#pragma unroll
            for (int nt = 0; nt < 8; nt++) {
                int key = nt * 8 + g, c = 8 * ks + tg;
                unsigned bh0 = Khi[key][c], bh1 = Khi[key][c + 4];
                unsigned bl0 = Klo[key][c], bl1 = Klo[key][c + 4];
                mma_bf16(S[nt], qh[ks], bh0, bh1);
                mma_bf16(S[nt], qh[ks], bl0, bl1);
                mma_bf16(S[nt], ql[ks], bh0, bh1);
            }

        int lr = 16 * w + g;
#pragma unroll
        for (int nt = 0; nt < 8; nt++) {
            int c0 = nt * 8 + 2 * tg;
            S[nt][0] = S[nt][0] * sc + rpesh[hopsh[lr][c0]];
            S[nt][1] = S[nt][1] * sc + rpesh[hopsh[lr][c0 + 1]];
            S[nt][2] = S[nt][2] * sc + rpesh[hopsh[lr + 8][c0]];
            S[nt][3] = S[nt][3] * sc + rpesh[hopsh[lr + 8][c0 + 1]];
        }

        float tm0 = -1e30f, tm1 = -1e30f;
#pragma unroll
        for (int nt = 0; nt < 8; nt++) {
            tm0 = fmaxf(tm0, fmaxf(S[nt][0], S[nt][1]));
            tm1 = fmaxf(tm1, fmaxf(S[nt][2], S[nt][3]));
        }
        tm0 = fmaxf(tm0, __shfl_xor_sync(0xffffffffu, tm0, 1));
        tm0 = fmaxf(tm0, __shfl_xor_sync(0xffffffffu, tm0, 2));
        tm1 = fmaxf(tm1, __shfl_xor_sync(0xffffffffu, tm1, 1));
        tm1 = fmaxf(tm1, __shfl_xor_sync(0xffffffffu, tm1, 2));
        float mn0 = fmaxf(mr0, tm0), mn1 = fmaxf(mr1, tm1);
        float al0 = ex2(mr0 - mn0), al1 = ex2(mr1 - mn1);
        mr0 = mn0; mr1 = mn1;
        float ps0 = 0.f, ps1 = 0.f;
#pragma unroll
        for (int nt = 0; nt < 8; nt++) {
            S[nt][0] = ex2(S[nt][0] - mn0);
            S[nt][1] = ex2(S[nt][1] - mn0);
            S[nt][2] = ex2(S[nt][2] - mn1);
            S[nt][3] = ex2(S[nt][3] - mn1);
            ps0 += S[nt][0] + S[nt][1];
            ps1 += S[nt][2] + S[nt][3];
        }
        ps0 += __shfl_xor_sync(0xffffffffu, ps0, 1);
        ps0 += __shfl_xor_sync(0xffffffffu, ps0, 2);
        ps1 += __shfl_xor_sync(0xffffffffu, ps1, 1);
        ps1 += __shfl_xor_sync(0xffffffffu, ps1, 2);
        l0 = l0 * al0 + ps0;
        l1 = l1 * al1 + ps1;
#pragma unroll
        for (int nt = 0; nt < 8; nt++) {
            O[nt][0] *= al0; O[nt][1] *= al0;
            O[nt][2] *= al1; O[nt][3] *= al1;
        }

        // O += P V : repack S C-frags as A-frags (2-term split), V via ldsm.trans
#pragma unroll
        for (int ks = 0; ks < 4; ks++) {
            unsigned ah2[4], al2[4];
            split2(S[2 * ks][0],     S[2 * ks][1],     ah2[0], al2[0]);
            split2(S[2 * ks][2],     S[2 * ks][3],     ah2[1], al2[1]);
            split2(S[2 * ks + 1][0], S[2 * ks + 1][1], ah2[2], al2[2]);
            split2(S[2 * ks + 1][2], S[2 * ks + 1][3], ah2[3], al2[3]);
            int vr = 16 * ks + (lane & 7) + ((lane >> 3) & 1) * 8;
            int vc = ((lane >> 4) & 1) * 4;
#pragma unroll
            for (int np = 0; np < 4; np++) {
                unsigned bh4[4], bl4[4];
                ldsm4t(bh4, &Vhi[vr][8 * np + vc]);
                ldsm4t(bl4, &Vlo[vr][8 * np + vc]);
                mma_bf16(O[2 * np],     ah2, bh4[0], bh4[1]);
                mma_bf16(O[2 * np],     ah2, bl4[0], bl4[1]);
                mma_bf16(O[2 * np],     al2, bh4[0], bh4[1]);
                mma_bf16(O[2 * np + 1], ah2, bh4[2], bh4[3]);
                mma_bf16(O[2 * np + 1], ah2, bl4[2], bl4[3]);
                mma_bf16(O[2 * np + 1], al2, bh4[2], bh4[3]);
            }
        }
        __syncthreads();
    }

    float inv0 = 1.f / l0, inv1 = 1.f / l1;
    int row = b * 1024 + q0 + 16 * w + g;
    size_t base0 = (size_t)row * 256 + h * 32, base8 = base0 + 8 * 256;
#pragma unroll
    for (int nt = 0; nt < 8; nt++) {
        unsigned uh, ul;
        split2(O[nt][0] * inv0, O[nt][1] * inv0, uh, ul);
        g_ohi[base0 + nt * 4 + tg] = uh; g_olo[base0 + nt * 4 + tg] = ul;
        split2(O[nt][2] * inv1, O[nt][3] * inv1, uh, ul);
        g_ohi[base8 + nt * 4 + tg] = uh; g_olo[base8 + nt * 4 + tg] = ul;
    }
}

__global__ __launch_bounds__(256) void out_mma(const float* __restrict__ bo,
                                               float* __restrict__ out) {
    __shared__ GSmem sm;
    const int t = threadIdx.x;
    const int m0 = blockIdx.y * 128, n0 = blockIdx.x * 128;
    float C[2][8][4];
    gemm128(sm, g_ohi, g_olo, g_whi[3], g_wlo[3], m0, n0, t, C);

    const int w = t >> 5, lane = t & 31, g = lane >> 2, tg = lane & 3;
    const int wm = w & 3, wn = w >> 2;
#pragma unroll
    for (int mt = 0; mt < 2; mt++) {
        int row = m0 + wm * 32 + mt * 16 + g;
#pragma unroll
        for (int nt = 0; nt < 8; nt++) {
            int col = n0 + wn * 64 + nt * 8 + 2 * tg;
            float2 b2 = *(const float2*)(bo + col);
            *(float2*)&out[(size_t)row * 512 + col] =
                make_float2(C[mt][nt][0] + b2.x, C[mt][nt][1] + b2.y);
            *(float2*)&out[(size_t)(row + 8) * 512 + col] =
                make_float2(C[mt][nt][2] + b2.x, C[mt][nt][3] + b2.y);
        }
    }
}

extern "C" void kernel_launch(void* const* d_in, const int* in_sizes, int n_in,
                              void* d_out, int out_size)
{
    const float* x   = (const float*)d_in[0];
    const float* Wq  = (const float*)d_in[1];
    const float* Wk  = (const float*)d_in[2];
    const float* Wv  = (const float*)d_in[3];
    const float* Wo  = (const float*)d_in[4];
    const float* bo  = (const float*)d_in[5];
    const float* rpe = (const float*)d_in[6];
    const int*   hop = (const int*)d_in[7];
    float* out = (float*)d_out;
    (void)in_sizes; (void)n_in; (void)out_size;

    split_kernel<<<16384, 256>>>(x, 0, 4194304);
    split_kernel<<<512, 256>>>(Wq, 1, 131072);
    split_kernel<<<512, 256>>>(Wk, 2, 131072);
    split_kernel<<<512, 256>>>(Wv, 3, 131072);
    split_kernel<<<512, 256>>>(Wo, 4, 131072);
    hop8_kernel<<<1024, 256>>>(hop, 262144);

    proj_mma<<<dim3(4, 128, 3), 256>>>();
    attn_mma<<<dim3(128, 8), 256>>>(rpe);
    out_mma<<<dim3(4, 128), 256>>>(bo, out);
}

// round 13
// speedup vs baseline: 3.5730x; 1.4326x over previous
#include <cuda_runtime.h>
#include <cuda_bf16.h>
#include <cuda_fp16.h>

#define Bv 16
#define Vv 1024
#define Dv 512
#define Hv 8
#define HDv 64

// bf16 split pairs (hi/lo) for the score-critical path (x, Wq, Wk, q, k)
__device__ unsigned g_xhi[4194304], g_xlo[4194304];     // X rows: 256 uints
__device__ unsigned g_whi[4][131072], g_wlo[2][131072]; // [0]=Wq,[1]=Wk bf16; [2]=Wv,[3]=Wo f16 single
__device__ unsigned g_xh16[4194304];                    // X as f16 pairs (for v-proj)
__device__ unsigned g_qhi[4194304], g_qlo[4194304];     // (B*H, V, 32 uints)
__device__ unsigned g_khi[4194304], g_klo[4194304];
__device__ unsigned g_vh16[4194304];                    // v as f16 pairs
__device__ unsigned g_oh16[4194304];                    // attn out as f16 pairs (B*V, 256 uints)
__device__ unsigned char g_hop8[1048576];

__device__ __forceinline__ void split2(float x, float y, unsigned &h, unsigned &l) {
    __nv_bfloat16 hx = __float2bfloat16_rn(x), hy = __float2bfloat16_rn(y);
    __nv_bfloat16 lx = __float2bfloat16_rn(x - __bfloat162float(hx));
    __nv_bfloat16 ly = __float2bfloat16_rn(y - __bfloat162float(hy));
    h = ((unsigned)__bfloat16_as_ushort(hy) << 16) | __bfloat16_as_ushort(hx);
    l = ((unsigned)__bfloat16_as_ushort(ly) << 16) | __bfloat16_as_ushort(lx);
}
__device__ __forceinline__ unsigned pkh2(float lo, float hi) {
    unsigned d; asm("cvt.rn.f16x2.f32 %0, %1, %2;" : "=r"(d) : "f"(hi), "f"(lo));
    return d;
}
__device__ __forceinline__ void mma_bf16(float c[4], const unsigned a[4],
                                         unsigned b0, unsigned b1) {
    asm volatile(
        "mma.sync.aligned.m16n8k16.row.col.f32.bf16.bf16.f32 "
        "{%0,%1,%2,%3}, {%4,%5,%6,%7}, {%8,%9}, {%0,%1,%2,%3};"
        : "+f"(c[0]), "+f"(c[1]), "+f"(c[2]), "+f"(c[3])
        : "r"(a[0]), "r"(a[1]), "r"(a[2]), "r"(a[3]), "r"(b0), "r"(b1));
}
__device__ __forceinline__ void mma_f16(float c[4], const unsigned a[4],
                                        unsigned b0, unsigned b1) {
    asm volatile(
        "mma.sync.aligned.m16n8k16.row.col.f32.f16.f16.f32 "
        "{%0,%1,%2,%3}, {%4,%5,%6,%7}, {%8,%9}, {%0,%1,%2,%3};"
        : "+f"(c[0]), "+f"(c[1]), "+f"(c[2]), "+f"(c[3])
        : "r"(a[0]), "r"(a[1]), "r"(a[2]), "r"(a[3]), "r"(b0), "r"(b1));
}
__device__ __forceinline__ void ldsm4t(unsigned r[4], const void* p) {
    unsigned a = (unsigned)__cvta_generic_to_shared(p);
    asm volatile("ldmatrix.sync.aligned.m8n8.x4.trans.shared.b16 {%0,%1,%2,%3}, [%4];"
        : "=r"(r[0]), "=r"(r[1]), "=r"(r[2]), "=r"(r[3]) : "r"(a));
}
__device__ __forceinline__ float ex2(float x) {
    float y; asm("ex2.approx.f32 %0, %1;" : "=f"(y) : "f"(x)); return y;
}

// ---------------- split kernels ----------------
__global__ void split_x(const float* __restrict__ in, int n2) {
    int i = blockIdx.x * blockDim.x + threadIdx.x;
    if (i >= n2) return;
    float2 v = ((const float2*)in)[i];
    unsigned h, l; split2(v.x, v.y, h, l);
    g_xhi[i] = h; g_xlo[i] = l;
    g_xh16[i] = pkh2(v.x, v.y);
}
__global__ void split_wbf(const float* __restrict__ in, int w, int n2) {
    int i = blockIdx.x * blockDim.x + threadIdx.x;
    if (i >= n2) return;
    float2 v = ((const float2*)in)[i];
    unsigned h, l; split2(v.x, v.y, h, l);
    g_whi[w][i] = h; g_wlo[w][i] = l;
}
__global__ void split_wh(const float* __restrict__ in, int w, int n2) {
    int i = blockIdx.x * blockDim.x + threadIdx.x;
    if (i >= n2) return;
    float2 v = ((const float2*)in)[i];
    g_whi[w][i] = pkh2(v.x, v.y);
}
__global__ void hop8_kernel(const int* __restrict__ hop, int n4) {
    int i = blockIdx.x * blockDim.x + threadIdx.x;
    if (i >= n4) return;
    int4 v = ((const int4*)hop)[i];
    ((unsigned*)g_hop8)[i] = (unsigned)(v.x & 0xff) | ((unsigned)(v.y & 0xff) << 8) |
        ((unsigned)(v.z & 0xff) << 16) | ((unsigned)(v.w & 0xff) << 24);
}

// ---------------------------------------------------------------------------
// bf16x3 128x128 GEMM (score-critical path, q/k projections)
// ---------------------------------------------------------------------------
struct GSmem { unsigned Ah[128][20], Al[128][20], Bh[128][20], Bl[128][20]; };

__device__ __forceinline__ void gemm128(
    GSmem& sm,
    const unsigned* __restrict__ Agh, const unsigned* __restrict__ Agl,
    const unsigned* __restrict__ Bgh, const unsigned* __restrict__ Bgl,
    int m0, int n0, int t, float C[2][8][4])
{
    const int w = t >> 5, lane = t & 31, g = lane >> 2, tg = lane & 3;
    const int wm = w & 3, wn = w >> 2;
#pragma unroll
    for (int mt = 0; mt < 2; mt++)
#pragma unroll
        for (int nt = 0; nt < 8; nt++)
#pragma unroll
            for (int j = 0; j < 4; j++) C[mt][nt][j] = 0.f;

    const int srow = t >> 1, scb = (t & 1) * 8;
    const unsigned* Ap  = Agh + (size_t)(m0 + srow) * 256 + scb;
    const unsigned* Alp = Agl + (size_t)(m0 + srow) * 256 + scb;
    const unsigned* Bp  = Bgh + (size_t)(n0 + srow) * 256 + scb;
    const unsigned* Blp = Bgl + (size_t)(n0 + srow) * 256 + scb;

    for (int k0 = 0; k0 < 256; k0 += 16) {
        uint4 a0 = *(const uint4*)(Ap + k0),  a1 = *(const uint4*)(Ap + k0 + 4);
        uint4 a2 = *(const uint4*)(Alp + k0), a3 = *(const uint4*)(Alp + k0 + 4);
        uint4 b0 = *(const uint4*)(Bp + k0),  b1 = *(const uint4*)(Bp + k0 + 4);
        uint4 b2 = *(const uint4*)(Blp + k0), b3 = *(const uint4*)(Blp + k0 + 4);
        __syncthreads();
        *(uint4*)&sm.Ah[srow][scb] = a0; *(uint4*)&sm.Ah[srow][scb + 4] = a1;
        *(uint4*)&sm.Al[srow][scb] = a2; *(uint4*)&sm.Al[srow][scb + 4] = a3;
        *(uint4*)&sm.Bh[srow][scb] = b0; *(uint4*)&sm.Bh[srow][scb + 4] = b1;
        *(uint4*)&sm.Bl[srow][scb] = b2; *(uint4*)&sm.Bl[srow][scb + 4] = b3;
        __syncthreads();
#pragma unroll
        for (int ks = 0; ks < 2; ks++) {
            unsigned ah[2][4], al[2][4];
#pragma unroll
            for (int mt = 0; mt < 2; mt++) {
                int r = wm * 32 + mt * 16 + g, c = 8 * ks + tg;
                ah[mt][0] = sm.Ah[r][c];     ah[mt][1] = sm.Ah[r + 8][c];
                ah[mt][2] = sm.Ah[r][c + 4]; ah[mt][3] = sm.Ah[r + 8][c + 4];
                al[mt][0] = sm.Al[r][c];     al[mt][1] = sm.Al[r + 8][c];
                al[mt][2] = sm.Al[r][c + 4]; al[mt][3] = sm.Al[r + 8][c + 4];
            }
#pragma unroll
            for (int nt = 0; nt < 8; nt++) {
                int n = wn * 64 + nt * 8 + g, c = 8 * ks + tg;
                unsigned bh0 = sm.Bh[n][c], bh1 = sm.Bh[n][c + 4];
                unsigned bl0 = sm.Bl[n][c], bl1 = sm.Bl[n][c + 4];
#pragma unroll
                for (int mt = 0; mt < 2; mt++) {
                    mma_bf16(C[mt][nt], ah[mt], bh0, bh1);
                    mma_bf16(C[mt][nt], ah[mt], bl0, bl1);
                    mma_bf16(C[mt][nt], al[mt], bh0, bh1);
                }
            }
        }
    }
}

// ---------------------------------------------------------------------------
// single-term f16 128x128 GEMM (v-projection, output projection)
// ---------------------------------------------------------------------------
struct HSmem { unsigned A[128][20], B[128][20]; };

__device__ __forceinline__ void gemm1h(
    HSmem& sm,
    const unsigned* __restrict__ Ag, const unsigned* __restrict__ Bg,
    int m0, int n0, int t, float C[2][8][4])
{
    const int w = t >> 5, lane = t & 31, g = lane >> 2, tg = lane & 3;
    const int wm = w & 3, wn = w >> 2;
#pragma unroll
    for (int mt = 0; mt < 2; mt++)
#pragma unroll
        for (int nt = 0; nt < 8; nt++)
#pragma unroll
            for (int j = 0; j < 4; j++) C[mt][nt][j] = 0.f;

    const int srow = t >> 1, scb = (t & 1) * 8;
    const unsigned* Ap = Ag + (size_t)(m0 + srow) * 256 + scb;
    const unsigned* Bp = Bg + (size_t)(n0 + srow) * 256 + scb;

    for (int k0 = 0; k0 < 256; k0 += 16) {
        uint4 a0 = *(const uint4*)(Ap + k0), a1 = *(const uint4*)(Ap + k0 + 4);
        uint4 b0 = *(const uint4*)(Bp + k0), b1 = *(const uint4*)(Bp + k0 + 4);
        __syncthreads();
        *(uint4*)&sm.A[srow][scb] = a0; *(uint4*)&sm.A[srow][scb + 4] = a1;
        *(uint4*)&sm.B[srow][scb] = b0; *(uint4*)&sm.B[srow][scb + 4] = b1;
        __syncthreads();
#pragma unroll
        for (int ks = 0; ks < 2; ks++) {
            unsigned a[2][4];
#pragma unroll
            for (int mt = 0; mt < 2; mt++) {
                int r = wm * 32 + mt * 16 + g, c = 8 * ks + tg;
                a[mt][0] = sm.A[r][c];     a[mt][1] = sm.A[r + 8][c];
                a[mt][2] = sm.A[r][c + 4]; a[mt][3] = sm.A[r + 8][c + 4];
            }
#pragma unroll
            for (int nt = 0; nt < 8; nt++) {
                int n = wn * 64 + nt * 8 + g, c = 8 * ks + tg;
                unsigned b0 = sm.B[n][c], b1 = sm.B[n][c + 4];
#pragma unroll
                for (int mt = 0; mt < 2; mt++)
                    mma_f16(C[mt][nt], a[mt], b0, b1);
            }
        }
    }
}

// q/k projections (bf16x3), z = 0 -> q, 1 -> k
__global__ __launch_bounds__(256) void proj_mma() {
    __shared__ GSmem sm;
    const unsigned *Bgh = g_whi[blockIdx.z], *Bgl = g_wlo[blockIdx.z];
    unsigned *Dh = blockIdx.z ? g_khi : g_qhi;
    unsigned *Dl = blockIdx.z ? g_klo : g_qlo;

    const int t = threadIdx.x;
    const int m0 = blockIdx.y * 128, n0 = blockIdx.x * 128;
    float C[2][8][4];
    gemm128(sm, g_xhi, g_xlo, Bgh, Bgl, m0, n0, t, C);

    const int w = t >> 5, lane = t & 31, g = lane >> 2, tg = lane & 3;
    const int wm = w & 3, wn = w >> 2;
#pragma unroll
    for (int mt = 0; mt < 2; mt++) {
        int row = m0 + wm * 32 + mt * 16 + g;
        int bb = row >> 10, vi = row & 1023;
#pragma unroll
        for (int nt = 0; nt < 8; nt++) {
            int col = n0 + wn * 64 + nt * 8 + 2 * tg;
            int hh = col >> 6, hd2 = (col & 63) >> 1;
            size_t idx = ((size_t)(bb * 8 + hh) * 1024 + vi) * 32 + hd2;
            unsigned uh, ul;
            split2(C[mt][nt][0], C[mt][nt][1], uh, ul);
            Dh[idx] = uh; Dl[idx] = ul;
            split2(C[mt][nt][2], C[mt][nt][3], uh, ul);
            Dh[idx + 256] = uh; Dl[idx + 256] = ul;
        }
    }
}

// v projection (f16 single-term)
__global__ __launch_bounds__(256) void projv_mma() {
    __shared__ HSmem sm;
    const int t = threadIdx.x;
    const int m0 = blockIdx.y * 128, n0 = blockIdx.x * 128;
    float C[2][8][4];
    gemm1h(sm, g_xh16, g_whi[2], m0, n0, t, C);

    const int w = t >> 5, lane = t & 31, g = lane >> 2, tg = lane & 3;
    const int wm = w & 3, wn = w >> 2;
#pragma unroll
    for (int mt = 0; mt < 2; mt++) {
        int row = m0 + wm * 32 + mt * 16 + g;
        int bb = row >> 10, vi = row & 1023;
#pragma unroll
        for (int nt = 0; nt < 8; nt++) {
            int col = n0 + wn * 64 + nt * 8 + 2 * tg;
            int hh = col >> 6, hd2 = (col & 63) >> 1;
            size_t idx = ((size_t)(bb * 8 + hh) * 1024 + vi) * 32 + hd2;
            g_vh16[idx]       = pkh2(C[mt][nt][0], C[mt][nt][1]);
            g_vh16[idx + 256] = pkh2(C[mt][nt][2], C[mt][nt][3]);
        }
    }
}

// ---------------------------------------------------------------------------
// Flash attention: S via bf16x3, P/V via single f16, l via ones-column MMA.
// ---------------------------------------------------------------------------
__global__ __launch_bounds__(256) void attn_mma(const float* __restrict__ rpe) {
    const int bh = blockIdx.x, b = bh >> 3, h = bh & 7;
    const int q0 = blockIdx.y * 128;
    const int t = threadIdx.x, w = t >> 5, lane = t & 31;
    const int g = lane >> 2, tg = lane & 3;
    const float L2E = 1.4426950408889634f;
    const unsigned ONES = 0x3C003C00u;  // f16x2 {1.0, 1.0}

    __shared__ unsigned Khi[64][36], Klo[64][36], Vsh[64][36];
    __shared__ unsigned char hopsh[128][80];
    __shared__ float rpesh[12];

    if (t < 9) rpesh[t] = rpe[h * 9 + t] * L2E;

    unsigned qh[4][4], ql[4][4];
    {
        const unsigned* qhp = g_qhi + (size_t)bh * 1024 * 32;
        const unsigned* qlp = g_qlo + (size_t)bh * 1024 * 32;
        int r0 = (q0 + 16 * w + g) * 32, r8 = r0 + 256;
#pragma unroll
        for (int ks = 0; ks < 4; ks++) {
            int c = 8 * ks + tg;
            qh[ks][0] = qhp[r0 + c]; qh[ks][1] = qhp[r8 + c];
            qh[ks][2] = qhp[r0 + c + 4]; qh[ks][3] = qhp[r8 + c + 4];
            ql[ks][0] = qlp[r0 + c]; ql[ks][1] = qlp[r8 + c];
            ql[ks][2] = qlp[r0 + c + 4]; ql[ks][3] = qlp[r8 + c + 4];
        }
    }

    float O[8][4];
#pragma unroll
    for (int nt = 0; nt < 8; nt++)
#pragma unroll
        for (int j = 0; j < 4; j++) O[nt][j] = 0.f;
    float Lacc[4] = {0.f, 0.f, 0.f, 0.f};
    float mr0 = -1e30f, mr1 = -1e30f;
    const size_t kvbase = (size_t)bh * 1024 * 32;
    const float sc = 0.125f * L2E;

    for (int kt = 0; kt < 1024; kt += 64) {
        {   // stage K hi/lo + V (f16): 64 keys x 32 uints each
            int key = t >> 2, cb = (t & 3) * 8;
            size_t go = kvbase + (size_t)(kt + key) * 32 + cb;
            const uint4* p;
            p = (const uint4*)(g_khi + go);
            *(uint4*)&Khi[key][cb] = p[0]; *(uint4*)&Khi[key][cb + 4] = p[1];
            p = (const uint4*)(g_klo + go);
            *(uint4*)&Klo[key][cb] = p[0]; *(uint4*)&Klo[key][cb + 4] = p[1];
            p = (const uint4*)(g_vh16 + go);
            *(uint4*)&Vsh[key][cb] = p[0]; *(uint4*)&Vsh[key][cb + 4] = p[1];
        }
        {   // stage hop bytes
            int r = t >> 1, c0 = (t & 1) * 32;
            const uint4* p = (const uint4*)(g_hop8 + (size_t)(q0 + r) * 1024 + kt + c0);
            *(uint4*)&hopsh[r][c0] = p[0];
            *(uint4*)&hopsh[r][c0 + 16] = p[1];
        }
        __syncthreads();

        float S[8][4];
#pragma unroll
        for (int nt = 0; nt < 8; nt++)
#pragma unroll
            for (int j = 0; j < 4; j++) S[nt][j] = 0.f;
#pragma unroll
        for (int ks = 0; ks < 4; ks++)
#pragma unroll
            for (int nt = 0; nt < 8; nt++) {
                int key = nt * 8 + g, c = 8 * ks + tg;
                unsigned bh0 = Khi[key][c], bh1 = Khi[key][c + 4];
                unsigned bl0 = Klo[key][c], bl1 = Klo[key][c + 4];
                mma_bf16(S[nt], qh[ks], bh0, bh1);
                mma_bf16(S[nt], qh[ks], bl0, bl1);
                mma_bf16(S[nt], ql[ks], bh0, bh1);
            }

        int lr = 16 * w + g;
#pragma unroll
        for (int nt = 0; nt < 8; nt++) {
            int c0 = nt * 8 + 2 * tg;
            S[nt][0] = S[nt][0] * sc + rpesh[hopsh[lr][c0]];
            S[nt][1] = S[nt][1] * sc + rpesh[hopsh[lr][c0 + 1]];
            S[nt][2] = S[nt][2] * sc + rpesh[hopsh[lr + 8][c0]];
            S[nt][3] = S[nt][3] * sc + rpesh[hopsh[lr + 8][c0 + 1]];
        }

        float tm0 = -1e30f, tm1 = -1e30f;
#pragma unroll
        for (int nt = 0; nt < 8; nt++) {
            tm0 = fmaxf(tm0, fmaxf(S[nt][0], S[nt][1]));
            tm1 = fmaxf(tm1, fmaxf(S[nt][2], S[nt][3]));
        }
        tm0 = fmaxf(tm0, __shfl_xor_sync(0xffffffffu, tm0, 1));
        tm0 = fmaxf(tm0, __shfl_xor_sync(0xffffffffu, tm0, 2));
        tm1 = fmaxf(tm1, __shfl_xor_sync(0xffffffffu, tm1, 1));
        tm1 = fmaxf(tm1, __shfl_xor_sync(0xffffffffu, tm1, 2));
        float mn0 = fmaxf(mr0, tm0), mn1 = fmaxf(mr1, tm1);
        float al0 = ex2(mr0 - mn0), al1 = ex2(mr1 - mn1);
        mr0 = mn0; mr1 = mn1;
#pragma unroll
        for (int nt = 0; nt < 8; nt++) {
            S[nt][0] = ex2(S[nt][0] - mn0);
            S[nt][1] = ex2(S[nt][1] - mn0);
            S[nt][2] = ex2(S[nt][2] - mn1);
            S[nt][3] = ex2(S[nt][3] - mn1);
        }
#pragma unroll
        for (int nt = 0; nt < 8; nt++) {
            O[nt][0] *= al0; O[nt][1] *= al0;
            O[nt][2] *= al1; O[nt][3] *= al1;
        }
        Lacc[0] *= al0; Lacc[1] *= al0; Lacc[2] *= al1; Lacc[3] *= al1;

        // O += P V (P single f16, V single f16); l via ones-column MMA
#pragma unroll
        for (int ks = 0; ks < 4; ks++) {
            unsigned ap[4];
            ap[0] = pkh2(S[2 * ks][0],     S[2 * ks][1]);
            ap[1] = pkh2(S[2 * ks][2],     S[2 * ks][3]);
            ap[2] = pkh2(S[2 * ks + 1][0], S[2 * ks + 1][1]);
            ap[3] = pkh2(S[2 * ks + 1][2], S[2 * ks + 1][3]);
            mma_f16(Lacc, ap, ONES, ONES);
            int vr = 16 * ks + (lane & 7) + ((lane >> 3) & 1) * 8;
            int vc = ((lane >> 4) & 1) * 4;
#pragma unroll
            for (int np = 0; np < 4; np++) {
                unsigned bv[4];
                ldsm4t(bv, &Vsh[vr][8 * np + vc]);
                mma_f16(O[2 * np],     ap, bv[0], bv[1]);
                mma_f16(O[2 * np + 1], ap, bv[2], bv[3]);
            }
        }
        __syncthreads();
    }

    float inv0 = 1.f / Lacc[0], inv1 = 1.f / Lacc[2];
    int row = b * 1024 + q0 + 16 * w + g;
    size_t base0 = (size_t)row * 256 + h * 32, base8 = base0 + 8 * 256;
#pragma unroll
    for (int nt = 0; nt < 8; nt++) {
        g_oh16[base0 + nt * 4 + tg] = pkh2(O[nt][0] * inv0, O[nt][1] * inv0);
        g_oh16[base8 + nt * 4 + tg] = pkh2(O[nt][2] * inv1, O[nt][3] * inv1);
    }
}

// output projection (f16 single-term) + bias
__global__ __launch_bounds__(256) void out_mma(const float* __restrict__ bo,
                                               float* __restrict__ out) {
    __shared__ HSmem sm;
    const int t = threadIdx.x;
    const int m0 = blockIdx.y * 128, n0 = blockIdx.x * 128;
    float C[2][8][4];
    gemm1h(sm, g_oh16, g_whi[3], m0, n0, t, C);

    const int w = t >> 5, lane = t & 31, g = lane >> 2, tg = lane & 3;
    const int wm = w & 3, wn = w >> 2;
#pragma unroll
    for (int mt = 0; mt < 2; mt++) {
        int row = m0 + wm * 32 + mt * 16 + g;
#pragma unroll
        for (int nt = 0; nt < 8; nt++) {
            int col = n0 + wn * 64 + nt * 8 + 2 * tg;
            float2 b2 = *(const float2*)(bo + col);
            *(float2*)&out[(size_t)row * 512 + col] =
                make_float2(C[mt][nt][0] + b2.x, C[mt][nt][1] + b2.y);
            *(float2*)&out[(size_t)(row + 8) * 512 + col] =
                make_float2(C[mt][nt][2] + b2.x, C[mt][nt][3] + b2.y);
        }
    }
}

extern "C" void kernel_launch(void* const* d_in, const int* in_sizes, int n_in,
                              void* d_out, int out_size)
{
    const float* x   = (const float*)d_in[0];
    const float* Wq  = (const float*)d_in[1];
    const float* Wk  = (const float*)d_in[2];
    const float* Wv  = (const float*)d_in[3];
    const float* Wo  = (const float*)d_in[4];
    const float* bo  = (const float*)d_in[5];
    const float* rpe = (const float*)d_in[6];
    const int*   hop = (const int*)d_in[7];
    float* out = (float*)d_out;
    (void)in_sizes; (void)n_in; (void)out_size;

    split_x<<<16384, 256>>>(x, 4194304);
    split_wbf<<<512, 256>>>(Wq, 0, 131072);
    split_wbf<<<512, 256>>>(Wk, 1, 131072);
    split_wh<<<512, 256>>>(Wv, 2, 131072);
    split_wh<<<512, 256>>>(Wo, 3, 131072);
    hop8_kernel<<<1024, 256>>>(hop, 262144);

    proj_mma<<<dim3(4, 128, 2), 256>>>();   // q, k
    projv_mma<<<dim3(4, 128), 256>>>();     // v
    attn_mma<<<dim3(128, 8), 256>>>(rpe);
    out_mma<<<dim3(4, 128), 256>>>(bo, out);
}

// round 17
// speedup vs baseline: 3.8131x; 1.0672x over previous
#include <cuda_runtime.h>
#include <cuda_bf16.h>
#include <cuda_fp16.h>

#define Bv 16
#define Vv 1024
#define Dv 512
#define Hv 8
#define HDv 64

// bf16 split pairs (hi/lo) for the score-critical path (x, Wq, Wk, q, k)
__device__ unsigned g_xhi[4194304], g_xlo[4194304];     // X rows: 256 uints
__device__ unsigned g_whi[4][131072], g_wlo[2][131072]; // [0]=Wq,[1]=Wk bf16; [2]=Wv,[3]=Wo f16 single
__device__ unsigned g_xh16[4194304];                    // X as f16 pairs (for v-proj)
__device__ unsigned g_qhi[4194304], g_qlo[4194304];     // (B*H, V, 32 uints)
__device__ unsigned g_khi[4194304], g_klo[4194304];
__device__ unsigned g_vh16[4194304];                    // v as f16 pairs
__device__ unsigned g_oh16[4194304];                    // attn out as f16 pairs (B*V, 256 uints)
__device__ unsigned char g_hop8[1048576];

__device__ __forceinline__ void split2(float x, float y, unsigned &h, unsigned &l) {
    __nv_bfloat16 hx = __float2bfloat16_rn(x), hy = __float2bfloat16_rn(y);
    __nv_bfloat16 lx = __float2bfloat16_rn(x - __bfloat162float(hx));
    __nv_bfloat16 ly = __float2bfloat16_rn(y - __bfloat162float(hy));
    h = ((unsigned)__bfloat16_as_ushort(hy) << 16) | __bfloat16_as_ushort(hx);
    l = ((unsigned)__bfloat16_as_ushort(ly) << 16) | __bfloat16_as_ushort(lx);
}
__device__ __forceinline__ unsigned pkh2(float lo, float hi) {
    unsigned d; asm("cvt.rn.f16x2.f32 %0, %1, %2;" : "=r"(d) : "f"(hi), "f"(lo));
    return d;
}
__device__ __forceinline__ void mma_bf16(float c[4], const unsigned a[4],
                                         unsigned b0, unsigned b1) {
    asm volatile(
        "mma.sync.aligned.m16n8k16.row.col.f32.bf16.bf16.f32 "
        "{%0,%1,%2,%3}, {%4,%5,%6,%7}, {%8,%9}, {%0,%1,%2,%3};"
        : "+f"(c[0]), "+f"(c[1]), "+f"(c[2]), "+f"(c[3])
        : "r"(a[0]), "r"(a[1]), "r"(a[2]), "r"(a[3]), "r"(b0), "r"(b1));
}
__device__ __forceinline__ void mma_f16(float c[4], const unsigned a[4],
                                        unsigned b0, unsigned b1) {
    asm volatile(
        "mma.sync.aligned.m16n8k16.row.col.f32.f16.f16.f32 "
        "{%0,%1,%2,%3}, {%4,%5,%6,%7}, {%8,%9}, {%0,%1,%2,%3};"
        : "+f"(c[0]), "+f"(c[1]), "+f"(c[2]), "+f"(c[3])
        : "r"(a[0]), "r"(a[1]), "r"(a[2]), "r"(a[3]), "r"(b0), "r"(b1));
}
__device__ __forceinline__ void ldsm4t(unsigned r[4], const void* p) {
    unsigned a = (unsigned)__cvta_generic_to_shared(p);
    asm volatile("ldmatrix.sync.aligned.m8n8.x4.trans.shared.b16 {%0,%1,%2,%3}, [%4];"
        : "=r"(r[0]), "=r"(r[1]), "=r"(r[2]), "=r"(r[3]) : "r"(a));
}
__device__ __forceinline__ float ex2(float x) {
    float y; asm("ex2.approx.f32 %0, %1;" : "=f"(y) : "f"(x)); return y;
}
__device__ __forceinline__ void cpa16(unsigned saddr, const void* g) {
    asm volatile("cp.async.cg.shared.global [%0], [%1], 16;" :: "r"(saddr), "l"(g));
}

// ---------------- fused prep kernel (splits + hop pack) ----------------
__global__ void prep_kernel(const float* __restrict__ x,
                            const float* __restrict__ Wq,
                            const float* __restrict__ Wk,
                            const float* __restrict__ Wv,
                            const float* __restrict__ Wo,
                            const int*   __restrict__ hop) {
    int i = blockIdx.x * blockDim.x + threadIdx.x;   // 0..4194303
    {
        float2 v = ((const float2*)x)[i];
        unsigned h, l; split2(v.x, v.y, h, l);
        g_xhi[i] = h; g_xlo[i] = l;
        g_xh16[i] = pkh2(v.x, v.y);
    }
    if (i < 131072) {
        float2 v = ((const float2*)Wq)[i];
        unsigned h, l; split2(v.x, v.y, h, l);
        g_whi[0][i] = h; g_wlo[0][i] = l;
        v = ((const float2*)Wk)[i];
        split2(v.x, v.y, h, l);
        g_whi[1][i] = h; g_wlo[1][i] = l;
        v = ((const float2*)Wv)[i];
        g_whi[2][i] = pkh2(v.x, v.y);
        v = ((const float2*)Wo)[i];
        g_whi[3][i] = pkh2(v.x, v.y);
    }
    if (i < 262144) {
        int4 v = ((const int4*)hop)[i];
        ((unsigned*)g_hop8)[i] = (unsigned)(v.x & 0xff) | ((unsigned)(v.y & 0xff) << 8) |
            ((unsigned)(v.z & 0xff) << 16) | ((unsigned)(v.w & 0xff) << 24);
    }
}

// ---------------------------------------------------------------------------
// bf16x3 128x128 GEMM (score path). Register-prefetch pipelined k-loop.
// ---------------------------------------------------------------------------
struct GSmem { unsigned Ah[128][20], Al[128][20], Bh[128][20], Bl[128][20]; };

__device__ __forceinline__ void gemm128(
    GSmem& sm,
    const unsigned* __restrict__ Agh, const unsigned* __restrict__ Agl,
    const unsigned* __restrict__ Bgh, const unsigned* __restrict__ Bgl,
    int m0, int n0, int t, float C[2][8][4])
{
    const int w = t >> 5, lane = t & 31, g = lane >> 2, tg = lane & 3;
    const int wm = w & 3, wn = w >> 2;
#pragma unroll
    for (int mt = 0; mt < 2; mt++)
#pragma unroll
        for (int nt = 0; nt < 8; nt++)
#pragma unroll
            for (int j = 0; j < 4; j++) C[mt][nt][j] = 0.f;

    const int srow = t >> 1, scb = (t & 1) * 8;
    const unsigned* Ap  = Agh + (size_t)(m0 + srow) * 256 + scb;
    const unsigned* Alp = Agl + (size_t)(m0 + srow) * 256 + scb;
    const unsigned* Bp  = Bgh + (size_t)(n0 + srow) * 256 + scb;
    const unsigned* Blp = Bgl + (size_t)(n0 + srow) * 256 + scb;

    uint4 a0 = *(const uint4*)(Ap),      a1 = *(const uint4*)(Ap + 4);
    uint4 a2 = *(const uint4*)(Alp),     a3 = *(const uint4*)(Alp + 4);
    uint4 b0 = *(const uint4*)(Bp),      b1 = *(const uint4*)(Bp + 4);
    uint4 b2 = *(const uint4*)(Blp),     b3 = *(const uint4*)(Blp + 4);

    for (int k0 = 0; k0 < 256; k0 += 16) {
        __syncthreads();
        *(uint4*)&sm.Ah[srow][scb] = a0; *(uint4*)&sm.Ah[srow][scb + 4] = a1;
        *(uint4*)&sm.Al[srow][scb] = a2; *(uint4*)&sm.Al[srow][scb + 4] = a3;
        *(uint4*)&sm.Bh[srow][scb] = b0; *(uint4*)&sm.Bh[srow][scb + 4] = b1;
        *(uint4*)&sm.Bl[srow][scb] = b2; *(uint4*)&sm.Bl[srow][scb + 4] = b3;
        __syncthreads();
        int k2 = (k0 + 16) & 255;   // wraps on last iter: harmless, never stored
        a0 = *(const uint4*)(Ap + k2);  a1 = *(const uint4*)(Ap + k2 + 4);
        a2 = *(const uint4*)(Alp + k2); a3 = *(const uint4*)(Alp + k2 + 4);
        b0 = *(const uint4*)(Bp + k2);  b1 = *(const uint4*)(Bp + k2 + 4);
        b2 = *(const uint4*)(Blp + k2); b3 = *(const uint4*)(Blp + k2 + 4);
#pragma unroll
        for (int ks = 0; ks < 2; ks++) {
            unsigned ah[2][4], al[2][4];
#pragma unroll
            for (int mt = 0; mt < 2; mt++) {
                int r = wm * 32 + mt * 16 + g, c = 8 * ks + tg;
                ah[mt][0] = sm.Ah[r][c];     ah[mt][1] = sm.Ah[r + 8][c];
                ah[mt][2] = sm.Ah[r][c + 4]; ah[mt][3] = sm.Ah[r + 8][c + 4];
                al[mt][0] = sm.Al[r][c];     al[mt][1] = sm.Al[r + 8][c];
                al[mt][2] = sm.Al[r][c + 4]; al[mt][3] = sm.Al[r + 8][c + 4];
            }
#pragma unroll
            for (int nt = 0; nt < 8; nt++) {
                int n = wn * 64 + nt * 8 + g, c = 8 * ks + tg;
                unsigned bh0 = sm.Bh[n][c], bh1 = sm.Bh[n][c + 4];
                unsigned bl0 = sm.Bl[n][c], bl1 = sm.Bl[n][c + 4];
#pragma unroll
                for (int mt = 0; mt < 2; mt++) {
                    mma_bf16(C[mt][nt], ah[mt], bh0, bh1);
                    mma_bf16(C[mt][nt], ah[mt], bl0, bl1);
                    mma_bf16(C[mt][nt], al[mt], bh0, bh1);
                }
            }
        }
    }
}

// ---------------------------------------------------------------------------
// single-term f16 128x128 GEMM, register-prefetch pipelined.
// ---------------------------------------------------------------------------
struct HSmem { unsigned A[128][20], B[128][20]; };

__device__ __forceinline__ void gemm1h(
    HSmem& sm,
    const unsigned* __restrict__ Ag, const unsigned* __restrict__ Bg,
    int m0, int n0, int t, float C[2][8][4])
{
    const int w = t >> 5, lane = t & 31, g = lane >> 2, tg = lane & 3;
    const int wm = w & 3, wn = w >> 2;
#pragma unroll
    for (int mt = 0; mt < 2; mt++)
#pragma unroll
        for (int nt = 0; nt < 8; nt++)
#pragma unroll
            for (int j = 0; j < 4; j++) C[mt][nt][j] = 0.f;

    const int srow = t >> 1, scb = (t & 1) * 8;
    const unsigned* Ap = Ag + (size_t)(m0 + srow) * 256 + scb;
    const unsigned* Bp = Bg + (size_t)(n0 + srow) * 256 + scb;

    uint4 a0 = *(const uint4*)(Ap), a1 = *(const uint4*)(Ap + 4);
    uint4 b0 = *(const uint4*)(Bp), b1 = *(const uint4*)(Bp + 4);

    for (int k0 = 0; k0 < 256; k0 += 16) {
        __syncthreads();
        *(uint4*)&sm.A[srow][scb] = a0; *(uint4*)&sm.A[srow][scb + 4] = a1;
        *(uint4*)&sm.B[srow][scb] = b0; *(uint4*)&sm.B[srow][scb + 4] = b1;
        __syncthreads();
        int k2 = (k0 + 16) & 255;
        a0 = *(const uint4*)(Ap + k2); a1 = *(const uint4*)(Ap + k2 + 4);
        b0 = *(const uint4*)(Bp + k2); b1 = *(const uint4*)(Bp + k2 + 4);
#pragma unroll
        for (int ks = 0; ks < 2; ks++) {
            unsigned a[2][4];
#pragma unroll
            for (int mt = 0; mt < 2; mt++) {
                int r = wm * 32 + mt * 16 + g, c = 8 * ks + tg;
                a[mt][0] = sm.A[r][c];     a[mt][1] = sm.A[r + 8][c];
                a[mt][2] = sm.A[r][c + 4]; a[mt][3] = sm.A[r + 8][c + 4];
            }
#pragma unroll
            for (int nt = 0; nt < 8; nt++) {
                int n = wn * 64 + nt * 8 + g, c = 8 * ks + tg;
                unsigned bb0 = sm.B[n][c], bb1 = sm.B[n][c + 4];
#pragma unroll
                for (int mt = 0; mt < 2; mt++)
                    mma_f16(C[mt][nt], a[mt], bb0, bb1);
            }
        }
    }
}

// q/k projections (bf16x3), z = 0 -> q, 1 -> k
__global__ __launch_bounds__(256) void proj_mma() {
    __shared__ GSmem sm;
    const unsigned *Bgh = g_whi[blockIdx.z], *Bgl = g_wlo[blockIdx.z];
    unsigned *Dh = blockIdx.z ? g_khi : g_qhi;
    unsigned *Dl = blockIdx.z ? g_klo : g_qlo;

    const int t = threadIdx.x;
    const int m0 = blockIdx.y * 128, n0 = blockIdx.x * 128;
    float C[2][8][4];
    gemm128(sm, g_xhi, g_xlo, Bgh, Bgl, m0, n0, t, C);

    const int w = t >> 5, lane = t & 31, g = lane >> 2, tg = lane & 3;
    const int wm = w & 3, wn = w >> 2;
#pragma unroll
    for (int mt = 0; mt < 2; mt++) {
        int row = m0 + wm * 32 + mt * 16 + g;
        int bb = row >> 10, vi = row & 1023;
#pragma unroll
        for (int nt = 0; nt < 8; nt++) {
            int col = n0 + wn * 64 + nt * 8 + 2 * tg;
            int hh = col >> 6, hd2 = (col & 63) >> 1;
            size_t idx = ((size_t)(bb * 8 + hh) * 1024 + vi) * 32 + hd2;
            unsigned uh, ul;
            split2(C[mt][nt][0], C[mt][nt][1], uh, ul);
            Dh[idx] = uh; Dl[idx] = ul;
            split2(C[mt][nt][2], C[mt][nt][3], uh, ul);
            Dh[idx + 256] = uh; Dl[idx + 256] = ul;
        }
    }
}

// v projection (f16 single-term)
__global__ __launch_bounds__(256) void projv_mma() {
    __shared__ HSmem sm;
    const int t = threadIdx.x;
    const int m0 = blockIdx.y * 128, n0 = blockIdx.x * 128;
    float C[2][8][4];
    gemm1h(sm, g_xh16, g_whi[2], m0, n0, t, C);

    const int w = t >> 5, lane = t & 31, g = lane >> 2, tg = lane & 3;
    const int wm = w & 3, wn = w >> 2;
#pragma unroll
    for (int mt = 0; mt < 2; mt++) {
        int row = m0 + wm * 32 + mt * 16 + g;
        int bb = row >> 10, vi = row & 1023;
#pragma unroll
        for (int nt = 0; nt < 8; nt++) {
            int col = n0 + wn * 64 + nt * 8 + 2 * tg;
            int hh = col >> 6, hd2 = (col & 63) >> 1;
            size_t idx = ((size_t)(bb * 8 + hh) * 1024 + vi) * 32 + hd2;
            g_vh16[idx]       = pkh2(C[mt][nt][0], C[mt][nt][1]);
            g_vh16[idx + 256] = pkh2(C[mt][nt][2], C[mt][nt][3]);
        }
    }
}

// ---------------------------------------------------------------------------
// Flash attention with 2-stage cp.async double-buffered K/V/hop staging.
// Dynamic smem layout (bytes):
//   stage s in {0,1}: Khi @ s*27648, Klo @ +9216, Vsh @ +18432  (64x36 uints each)
//   hop  stage s:     55296 + s*10240  (128x80 bytes)
// total = 75776
// ---------------------------------------------------------------------------
#define ATTN_SMEM 75776

__global__ __launch_bounds__(256) void attn_mma(const float* __restrict__ rpe) {
    extern __shared__ unsigned char dsm[];
    __shared__ float rpesh[12];

    const int bh = blockIdx.x, b = bh >> 3, h = bh & 7;
    const int q0 = blockIdx.y * 128;
    const int t = threadIdx.x, w = t >> 5, lane = t & 31;
    const int g = lane >> 2, tg = lane & 3;
    const float L2E = 1.4426950408889634f;
    const unsigned ONES = 0x3C003C00u;

    if (t < 9) rpesh[t] = rpe[h * 9 + t] * L2E;

    const size_t kvbase = (size_t)bh * 1024 * 32;
    const unsigned sb = (unsigned)__cvta_generic_to_shared(dsm);

    // staging coordinates (per thread)
    const int skey = t >> 2, scb = (t & 3) * 8;
    const int hr = t >> 1, hc0 = (t & 1) * 32;

    // q fragments
    unsigned qh[4][4], ql[4][4];
    {
        const unsigned* qhp = g_qhi + kvbase;
        const unsigned* qlp = g_qlo + kvbase;
        int r0 = (q0 + 16 * w + g) * 32, r8 = r0 + 256;
#pragma unroll
        for (int ks = 0; ks < 4; ks++) {
            int c = 8 * ks + tg;
            qh[ks][0] = qhp[r0 + c]; qh[ks][1] = qhp[r8 + c];
            qh[ks][2] = qhp[r0 + c + 4]; qh[ks][3] = qhp[r8 + c + 4];
            ql[ks][0] = qlp[r0 + c]; ql[ks][1] = qlp[r8 + c];
            ql[ks][2] = qlp[r0 + c + 4]; ql[ks][3] = qlp[r8 + c + 4];
        }
    }

    float O[8][4];
#pragma unroll
    for (int nt = 0; nt < 8; nt++)
#pragma unroll
        for (int j = 0; j < 4; j++) O[nt][j] = 0.f;
    float Lacc[4] = {0.f, 0.f, 0.f, 0.f};
    float mr0 = -1e30f, mr1 = -1e30f;
    const float sc = 0.125f * L2E;

    // ---- stage loader (cp.async, 8x16B per thread) ----
    auto stage_load = [&](int s, int kt) {
        size_t go = kvbase + (size_t)(kt + skey) * 32 + scb;
        unsigned kof = sb + s * 27648 + (skey * 36 + scb) * 4;
        cpa16(kof,          g_khi + go); cpa16(kof + 16,          g_khi + go + 4);
        cpa16(kof + 9216,   g_klo + go); cpa16(kof + 9216 + 16,   g_klo + go + 4);
        cpa16(kof + 18432,  g_vh16 + go); cpa16(kof + 18432 + 16, g_vh16 + go + 4);
        unsigned hof = sb + 55296 + s * 10240 + hr * 80 + hc0;
        const unsigned char* hp = g_hop8 + (size_t)(q0 + hr) * 1024 + kt + hc0;
        cpa16(hof, hp); cpa16(hof + 16, hp + 16);
    };

    stage_load(0, 0);
    asm volatile("cp.async.commit_group;");

    for (int it = 0; it < 16; it++) {
        if (it < 15) {
            stage_load((it + 1) & 1, (it + 1) * 64);
            asm volatile("cp.async.commit_group;");
            asm volatile("cp.async.wait_group 1;");
        } else {
            asm volatile("cp.async.wait_group 0;");
        }
        __syncthreads();

        const int s = it & 1;
        unsigned (*Khi)[36] = (unsigned(*)[36])(dsm + s * 27648);
        unsigned (*Klo)[36] = (unsigned(*)[36])(dsm + s * 27648 + 9216);
        unsigned (*Vsh)[36] = (unsigned(*)[36])(dsm + s * 27648 + 18432);
        unsigned char (*hopsh)[80] = (unsigned char(*)[80])(dsm + 55296 + s * 10240);

        float S[8][4];
#pragma unroll
        for (int nt = 0; nt < 8; nt++)
#pragma unroll
            for (int j = 0; j < 4; j++) S[nt][j] = 0.f;
#pragma unroll
        for (int ks = 0; ks < 4; ks++)
#pragma unroll
            for (int nt = 0; nt < 8; nt++) {
                int key = nt * 8 + g, c = 8 * ks + tg;
                unsigned bh0 = Khi[key][c], bh1 = Khi[key][c + 4];
                unsigned bl0 = Klo[key][c], bl1 = Klo[key][c + 4];
                mma_bf16(S[nt], qh[ks], bh0, bh1);
                mma_bf16(S[nt], qh[ks], bl0, bl1);
                mma_bf16(S[nt], ql[ks], bh0, bh1);
            }

        int lr = 16 * w + g;
#pragma unroll
        for (int nt = 0; nt < 8; nt++) {
            int c0 = nt * 8 + 2 * tg;
            S[nt][0] = S[nt][0] * sc + rpesh[hopsh[lr][c0]];
            S[nt][1] = S[nt][1] * sc + rpesh[hopsh[lr][c0 + 1]];
            S[nt][2] = S[nt][2] * sc + rpesh[hopsh[lr + 8][c0]];
            S[nt][3] = S[nt][3] * sc + rpesh[hopsh[lr + 8][c0 + 1]];
        }

        float tm0 = -1e30f, tm1 = -1e30f;
#pragma unroll
        for (int nt = 0; nt < 8; nt++) {
            tm0 = fmaxf(tm0, fmaxf(S[nt][0], S[nt][1]));
            tm1 = fmaxf(tm1, fmaxf(S[nt][2], S[nt][3]));
        }
        tm0 = fmaxf(tm0, __shfl_xor_sync(0xffffffffu, tm0, 1));
        tm0 = fmaxf(tm0, __shfl_xor_sync(0xffffffffu, tm0, 2));
        tm1 = fmaxf(tm1, __shfl_xor_sync(0xffffffffu, tm1, 1));
        tm1 = fmaxf(tm1, __shfl_xor_sync(0xffffffffu, tm1, 2));
        float mn0 = fmaxf(mr0, tm0), mn1 = fmaxf(mr1, tm1);
        float al0 = ex2(mr0 - mn0), al1 = ex2(mr1 - mn1);
        mr0 = mn0; mr1 = mn1;
#pragma unroll
        for (int nt = 0; nt < 8; nt++) {
            S[nt][0] = ex2(S[nt][0] - mn0);
            S[nt][1] = ex2(S[nt][1] - mn0);
            S[nt][2] = ex2(S[nt][2] - mn1);
            S[nt][3] = ex2(S[nt][3] - mn1);
        }
#pragma unroll
        for (int nt = 0; nt < 8; nt++) {
            O[nt][0] *= al0; O[nt][1] *= al0;
            O[nt][2] *= al1; O[nt][3] *= al1;
        }
        Lacc[0] *= al0; Lacc[1] *= al0; Lacc[2] *= al1; Lacc[3] *= al1;

#pragma unroll
        for (int ks = 0; ks < 4; ks++) {
            unsigned ap[4];
            ap[0] = pkh2(S[2 * ks][0],     S[2 * ks][1]);
            ap[1] = pkh2(S[2 * ks][2],     S[2 * ks][3]);
            ap[2] = pkh2(S[2 * ks + 1][0], S[2 * ks + 1][1]);
            ap[3] = pkh2(S[2 * ks + 1][2], S[2 * ks + 1][3]);
            mma_f16(Lacc, ap, ONES, ONES);
            int vr = 16 * ks + (lane & 7) + ((lane >> 3) & 1) * 8;
            int vc = ((lane >> 4) & 1) * 4;
#pragma unroll
            for (int np = 0; np < 4; np++) {
                unsigned bv[4];
                ldsm4t(bv, &Vsh[vr][8 * np + vc]);
                mma_f16(O[2 * np],     ap, bv[0], bv[1]);
                mma_f16(O[2 * np + 1], ap, bv[2], bv[3]);
            }
        }
        __syncthreads();   // all warps done with stage s before it is re-staged
    }

    float inv0 = 1.f / Lacc[0], inv1 = 1.f / Lacc[2];
    int row = b * 1024 + q0 + 16 * w + g;
    size_t base0 = (size_t)row * 256 + h * 32, base8 = base0 + 8 * 256;
#pragma unroll
    for (int nt = 0; nt < 8; nt++) {
        g_oh16[base0 + nt * 4 + tg] = pkh2(O[nt][0] * inv0, O[nt][1] * inv0);
        g_oh16[base8 + nt * 4 + tg] = pkh2(O[nt][2] * inv1, O[nt][3] * inv1);
    }
}

// output projection (f16 single-term) + bias
__global__ __launch_bounds__(256) void out_mma(const float* __restrict__ bo,
                                               float* __restrict__ out) {
    __shared__ HSmem sm;
    const int t = threadIdx.x;
    const int m0 = blockIdx.y * 128, n0 = blockIdx.x * 128;
    float C[2][8][4];
    gemm1h(sm, g_oh16, g_whi[3], m0, n0, t, C);

    const int w = t >> 5, lane = t & 31, g = lane >> 2, tg = lane & 3;
    const int wm = w & 3, wn = w >> 2;
#pragma unroll
    for (int mt = 0; mt < 2; mt++) {
        int row = m0 + wm * 32 + mt * 16 + g;
#pragma unroll
        for (int nt = 0; nt < 8; nt++) {
            int col = n0 + wn * 64 + nt * 8 + 2 * tg;
            float2 b2 = *(const float2*)(bo + col);
            *(float2*)&out[(size_t)row * 512 + col] =
                make_float2(C[mt][nt][0] + b2.x, C[mt][nt][1] + b2.y);
            *(float2*)&out[(size_t)(row + 8) * 512 + col] =
                make_float2(C[mt][nt][2] + b2.x, C[mt][nt][3] + b2.y);
        }
    }
}

extern "C" void kernel_launch(void* const* d_in, const int* in_sizes, int n_in,
                              void* d_out, int out_size)
{
    const float* x   = (const float*)d_in[0];
    const float* Wq  = (const float*)d_in[1];
    const float* Wk  = (const float*)d_in[2];
    const float* Wv  = (const float*)d_in[3];
    const float* Wo  = (const float*)d_in[4];
    const float* bo  = (const float*)d_in[5];
    const float* rpe = (const float*)d_in[6];
    const int*   hop = (const int*)d_in[7];
    float* out = (float*)d_out;
    (void)in_sizes; (void)n_in; (void)out_size;

    cudaFuncSetAttribute(attn_mma, cudaFuncAttributeMaxDynamicSharedMemorySize,
                         ATTN_SMEM);

    prep_kernel<<<16384, 256>>>(x, Wq, Wk, Wv, Wo, hop);
    proj_mma<<<dim3(4, 128, 2), 256>>>();   // q, k
    projv_mma<<<dim3(4, 128), 256>>>();     // v
    attn_mma<<<dim3(128, 8), 256, ATTN_SMEM>>>(rpe);
    out_mma<<<dim3(4, 128), 256>>>(bo, out);
}